// round 17
// baseline (speedup 1.0000x reference)
#include <cuda_runtime.h>
#include <cuda_fp16.h>
#include <math.h>

#define BATCH 2
#define T 8
#define C 64
#define R 16
#define H 160
#define W 160
#define HW (H*W)            // 25600
#define CHW (C*HW)          // 1,638,400
#define TCHW (T*CHW)
#define C2 128
#define C4 256

typedef unsigned long long ull;

// ---------------- scratch (device globals; referenced ONLY from device code) ----
__device__ float g_pool_all[(T-1)*BATCH*C];
__device__ float g_wd_all[(T-1)*BATCH*C*9];
__device__ float g_fp[BATCH*CHW];
__device__ float g_fusion[(size_t)BATCH*C2*HW];
__device__ float g_a1[(size_t)BATCH*C4*HW];
__device__ float g_a2[(size_t)BATCH*C4*HW];
// conv weights pre-split fp16 hi/lo, ldmatrix-ready [tap][ch8][oc128][24]
__device__ __half g_whi[9*8*128*24];
__device__ __half g_wlo[9*8*128*24];
// expand weights [gate][ch4][oc256][24]
__device__ __half g_pwhi[2*4*256*24];
__device__ __half g_pwlo[2*4*256*24];
// contract weights [gate][ch16][oc64][24]
__device__ __half g_cwhi[2*16*64*24];
__device__ __half g_cwlo[2*16*64*24];

// ---------------- mma helpers -----------------------------------------------------
__device__ __forceinline__ void ldsm4(unsigned* r, const void* p) {
    unsigned s = (unsigned)__cvta_generic_to_shared(p);
    asm volatile("ldmatrix.sync.aligned.m8n8.x4.shared.b16 {%0,%1,%2,%3}, [%4];"
        : "=r"(r[0]), "=r"(r[1]), "=r"(r[2]), "=r"(r[3]) : "r"(s));
}
__device__ __forceinline__ void ldsm4t(unsigned* r, const void* p) {
    unsigned s = (unsigned)__cvta_generic_to_shared(p);
    asm volatile("ldmatrix.sync.aligned.m8n8.x4.trans.shared.b16 {%0,%1,%2,%3}, [%4];"
        : "=r"(r[0]), "=r"(r[1]), "=r"(r[2]), "=r"(r[3]) : "r"(s));
}
__device__ __forceinline__ void mma16816(float* d, const unsigned* a, const unsigned* b) {
    asm volatile("mma.sync.aligned.m16n8k16.row.col.f32.f16.f16.f32 "
        "{%0,%1,%2,%3},{%4,%5,%6,%7},{%8,%9},{%0,%1,%2,%3};"
        : "+f"(d[0]), "+f"(d[1]), "+f"(d[2]), "+f"(d[3])
        : "r"(a[0]), "r"(a[1]), "r"(a[2]), "r"(a[3]), "r"(b[0]), "r"(b[1]));
}
__device__ __forceinline__ void split2(float v, __half& h, __half& l) {
    h = __float2half_rn(v);
    l = __float2half_rn(v - __half2float(h));
}

// ---------------- pool for ALL steps (float4, verified R16) ------------------------
__global__ void pool_all_kernel(const float* __restrict__ feature) {
    int g = blockIdx.x;
    int step = g / (BATCH*C);
    int rem  = g % (BATCH*C);
    int bi = rem >> 6, c = rem & 63;
    const float4* p = (const float4*)(feature + (size_t)bi*TCHW + (size_t)step*CHW + (size_t)c*HW);
    float s = 0.f;
    for (int i = threadIdx.x; i < HW/4; i += 256) {
        float4 v = p[i];
        s += (v.x + v.y) + (v.z + v.w);
    }
    __shared__ float red[8];
    #pragma unroll
    for (int o = 16; o; o >>= 1) s += __shfl_down_sync(0xffffffffu, s, o);
    if ((threadIdx.x & 31) == 0) red[threadIdx.x >> 5] = s;
    __syncthreads();
    if (threadIdx.x == 0) {
        float t = 0.f;
        #pragma unroll
        for (int k = 0; k < 8; k++) t += red[k];
        g_pool_all[g] = t * (1.0f / (float)HW);
    }
}

// ---------------- tiny MLP for ALL steps ------------------------------------------
__global__ void mlp_all_kernel(const float* __restrict__ w1,
                               const float* __restrict__ gamma,
                               const float* __restrict__ beta,
                               const float* __restrict__ mean,
                               const float* __restrict__ var,
                               const float* __restrict__ w2,
                               const float* __restrict__ b2) {
    __shared__ float zs[BATCH*R];
    int step = blockIdx.x;
    int tid = threadIdx.x;
    const float* pool = g_pool_all + step*BATCH*C;
    float* wd = g_wd_all + step*BATCH*C*9;
    if (tid < BATCH*R) {
        int bi = tid / R, j = tid % R;
        float s = 0.f;
        for (int c = 0; c < C; c++) s = fmaf(pool[bi*C + c], w1[j*C + c], s);
        s = (s - mean[j]) * rsqrtf(var[j] + 1e-5f) * gamma[j] + beta[j];
        zs[tid] = fmaxf(s, 0.f);
    }
    __syncthreads();
    for (int o = tid; o < BATCH*C*9; o += blockDim.x) {
        int bi = o / (C*9), oo = o % (C*9);
        float s = b2[oo];
        #pragma unroll
        for (int j = 0; j < R; j++) s = fmaf(zs[bi*R + j], w2[oo*R + j], s);
        wd[o] = s;
    }
}

// ---------------- dynamic depthwise 3x3, 4px/thread (verified R15) ----------------
__global__ void __launch_bounds__(256) dyndw_kernel(const float* __restrict__ ybase,
                                                    const float* __restrict__ kc_bias, int step) {
    int g = blockIdx.x * 256 + threadIdx.x;
    int px4   = g % (HW/4);
    int plane = g / (HW/4);
    int c = plane & 63, bi = plane >> 6;
    int y  = px4 / (W/4);
    int x0 = (px4 % (W/4)) * 4;

    const float* p = ybase + (size_t)bi*TCHW + (size_t)c*HW;
    const float* wp = g_wd_all + step*BATCH*C*9 + plane*9;
    float w[9];
    #pragma unroll
    for (int k = 0; k < 9; k++) w[k] = wp[k];

    float A[3][6];
    #pragma unroll
    for (int kh = 0; kh < 3; kh++) {
        int yy = y + kh - 1;
        if ((unsigned)yy < H) {
            const float* row = p + yy*W;
            float4 m = *((const float4*)(row + x0));
            A[kh][0] = (x0 > 0)      ? row[x0 - 1] : 0.f;
            A[kh][1] = m.x; A[kh][2] = m.y; A[kh][3] = m.z; A[kh][4] = m.w;
            A[kh][5] = (x0 + 4 < W)  ? row[x0 + 4] : 0.f;
        } else {
            #pragma unroll
            for (int j = 0; j < 6; j++) A[kh][j] = 0.f;
        }
    }

    float bv = kc_bias[c];
    float r[4];
    #pragma unroll
    for (int j = 0; j < 4; j++) {
        float s = bv;
        #pragma unroll
        for (int kh = 0; kh < 3; kh++)
            #pragma unroll
            for (int kw = 0; kw < 3; kw++)
                s = fmaf(A[kh][j + kw], w[kh*3 + kw], s);
        r[j] = s;
    }
    *((float4*)(g_fp + (size_t)plane*HW + (size_t)y*W + x0)) = make_float4(r[0], r[1], r[2], r[3]);
}

// ---------------- weight split preps (once per launch) ---------------------------
__global__ void prep_w_kernel(const float* __restrict__ conv1_w) {
    int idx = blockIdx.x * 256 + threadIdx.x;
    if (idx >= 9*8*128*16) return;
    int k   = idx & 15;
    int oc  = (idx >> 4) & 127;
    int ch  = (idx >> 11) & 7;
    int tap = idx >> 14;
    int ic = ch*16 + k;
    float v = conv1_w[((size_t)oc*C2 + ic)*9 + tap];
    __half h, l; split2(v, h, l);
    size_t o = ((size_t)(tap*8 + ch)*128 + oc)*24 + k;
    g_whi[o] = h; g_wlo[o] = l;
}
__global__ void prep_pw_kernel(const float* __restrict__ pi1_w, const float* __restrict__ pi2_w) {
    int idx = blockIdx.x * 256 + threadIdx.x;
    if (idx >= 2*4*256*16) return;
    int k    = idx & 15;
    int oc   = (idx >> 4) & 255;
    int ch   = (idx >> 12) & 3;
    int gate = idx >> 14;
    const float* w = gate ? pi2_w : pi1_w;
    float v = w[(size_t)oc*C + ch*16 + k];
    __half h, l; split2(v, h, l);
    size_t o = ((size_t)(gate*4 + ch)*256 + oc)*24 + k;
    g_pwhi[o] = h; g_pwlo[o] = l;
}
__global__ void prep_cw_kernel(const float* __restrict__ po1_w, const float* __restrict__ po2_w) {
    int idx = blockIdx.x * 256 + threadIdx.x;
    if (idx >= 2*16*64*16) return;
    int k    = idx & 15;
    int oc   = (idx >> 4) & 63;
    int ch   = (idx >> 10) & 15;
    int gate = idx >> 14;
    const float* w = gate ? po2_w : po1_w;
    float v = w[(size_t)oc*C4 + ch*16 + k];
    __half h, l; split2(v, h, l);
    size_t o = ((size_t)(gate*16 + ch)*64 + oc)*24 + k;
    g_cwhi[o] = h; g_cwlo[o] = l;
}

// ---------------- conv3x3 via fp16-split mma, all-taps W preload (R16) ------------
#define CONV_SMEM ((204*24*2 + 9*3072*2)*2)
__global__ void __launch_bounds__(512, 1) conv_mma_kernel(const float* __restrict__ xbase,
                                                          const float* __restrict__ bias) {
    extern __shared__ __align__(16) __half sm[];
    __half* Xhi_s = sm;
    __half* Xlo_s = sm + 204*24;
    __half* Whi_s = sm + 2*204*24;
    __half* Wlo_s = sm + 2*204*24 + 9*3072;

    int tid = threadIdx.x;
    int lane = tid & 31, wid = tid >> 5;
    int wm = wid & 3, wn = wid >> 2;
    int x0 = blockIdx.x * 32;
    int y0 = blockIdx.y * 4;
    int bi = blockIdx.z;

    const float* xp  = xbase + (size_t)bi*TCHW;
    const float* fpp = g_fp  + (size_t)bi*CHW;

    float acc[2][4][4];
    #pragma unroll
    for (int m = 0; m < 2; m++)
        #pragma unroll
        for (int n = 0; n < 4; n++)
            #pragma unroll
            for (int r = 0; r < 4; r++) acc[m][n][r] = 0.f;

    int ic_l = tid >> 5;
    int rg   = tid & 31;
    int hgoff[7]; bool hval[7]; int hsm[7];
    #pragma unroll
    for (int j = 0; j < 7; j++) {
        int r = rg + j*32;
        bool ok = r < 204;
        int ry = r / 34, rx = r - ry*34;
        int gy = y0 + ry - 1, gx = x0 + rx - 1;
        bool v = ok && ((unsigned)gy < H) && ((unsigned)gx < W);
        hval[j] = v;
        hgoff[j] = v ? gy*W + gx : 0;
        hsm[j] = ok ? (r*24 + ic_l) : -1;
    }

    int a_row = (lane & 7) + ((lane >> 3) & 1)*8;
    int a_col = (lane >> 4)*8;
    int b_n   = (lane & 7) + ((lane >> 4) & 1)*8;
    int b_col = ((lane >> 3) & 1)*8;
    const char* bPtrHi[2];
    const char* bPtrLo[2];
    #pragma unroll
    for (int p = 0; p < 2; p++) {
        int n = wn*32 + p*16 + b_n;
        int row0 = ((n >> 5) + 1)*34 + (n & 31) + 1;
        bPtrHi[p] = (const char*)Xhi_s + row0*48 + b_col*2;
        bPtrLo[p] = (const char*)Xlo_s + row0*48 + b_col*2;
    }

    for (int ch = 0; ch < 8; ch++) {
        __syncthreads();
        {
            int ic = ch*16 + ic_l;
            const float* pl = (ic < C) ? (xp + (size_t)ic*HW) : (fpp + (size_t)(ic - C)*HW);
            #pragma unroll
            for (int j = 0; j < 7; j++) {
                if (hsm[j] >= 0) {
                    float v = hval[j] ? __ldg(pl + hgoff[j]) : 0.f;
                    __half h, l; split2(v, h, l);
                    Xhi_s[hsm[j]] = h;
                    Xlo_s[hsm[j]] = l;
                }
            }
        }
        {
            #pragma unroll
            for (int i = 0; i < 7; i++) {
                int flat = tid + 512*i;
                if (flat < 3456) {
                    int t = flat / 384;
                    int e = flat - t*384;
                    ((float4*)(Whi_s + t*3072))[e] = ((const float4*)(g_whi + (size_t)(t*8 + ch)*3072))[e];
                    ((float4*)(Wlo_s + t*3072))[e] = ((const float4*)(g_wlo + (size_t)(t*8 + ch)*3072))[e];
                }
            }
        }
        __syncthreads();

        #pragma unroll
        for (int tap = 0; tap < 9; tap++) {
            int dy = tap/3 - 1, dx = tap%3 - 1;
            int tapoff = (dy*34 + dx)*48;
            const __half* Wb_hi = Whi_s + tap*3072;
            const __half* Wb_lo = Wlo_s + tap*3072;

            unsigned Ahi[2][4], Alo[2][4];
            ldsm4(Ahi[0], &Wb_hi[(wm*32 +      a_row)*24 + a_col]);
            ldsm4(Ahi[1], &Wb_hi[(wm*32 + 16 + a_row)*24 + a_col]);
            ldsm4(Alo[0], &Wb_lo[(wm*32 +      a_row)*24 + a_col]);
            ldsm4(Alo[1], &Wb_lo[(wm*32 + 16 + a_row)*24 + a_col]);
            unsigned Bhi[4][2], Blo[4][2];
            #pragma unroll
            for (int p = 0; p < 2; p++) {
                unsigned t[4];
                ldsm4(t, bPtrHi[p] + tapoff);
                Bhi[2*p][0] = t[0]; Bhi[2*p][1] = t[1];
                Bhi[2*p+1][0] = t[2]; Bhi[2*p+1][1] = t[3];
                ldsm4(t, bPtrLo[p] + tapoff);
                Blo[2*p][0] = t[0]; Blo[2*p][1] = t[1];
                Blo[2*p+1][0] = t[2]; Blo[2*p+1][1] = t[3];
            }
            #pragma unroll
            for (int m = 0; m < 2; m++)
                #pragma unroll
                for (int n = 0; n < 4; n++) {
                    mma16816(acc[m][n], Ahi[m], Bhi[n]);
                    mma16816(acc[m][n], Ahi[m], Blo[n]);
                    mma16816(acc[m][n], Alo[m], Bhi[n]);
                }
        }
    }

    int row_ = lane >> 2;
    int colp = (lane & 3)*2;
    int yo = y0 + wn;
    #pragma unroll
    for (int m = 0; m < 2; m++) {
        int ocA = wm*32 + m*16 + row_;
        int ocB = ocA + 8;
        float bA = bias[ocA], bB = bias[ocB];
        #pragma unroll
        for (int n = 0; n < 4; n++) {
            int xo = x0 + n*8 + colp;
            float v0 = acc[m][n][0] + bA, v1 = acc[m][n][1] + bA;
            float v2 = acc[m][n][2] + bB, v3 = acc[m][n][3] + bB;
            v0 = (v0 > 0.f) ? v0 : 0.1f*v0;
            v1 = (v1 > 0.f) ? v1 : 0.1f*v1;
            v2 = (v2 > 0.f) ? v2 : 0.1f*v2;
            v3 = (v3 > 0.f) ? v3 : 0.1f*v3;
            *((float2*)(g_fusion + ((size_t)bi*C2 + ocA)*HW + (size_t)yo*W + xo)) = make_float2(v0, v1);
            *((float2*)(g_fusion + ((size_t)bi*C2 + ocB)*HW + (size_t)yo*W + xo)) = make_float2(v2, v3);
        }
    }
}

// ---------------- expand via mma, [k][px] X + trans (verified R14): K=64 ----------
#define EPS 72
__global__ void __launch_bounds__(256, 2) expand_mma_kernel(const float* __restrict__ b1,
                                                            const float* __restrict__ b2) {
    __shared__ __align__(16) __half Whi_s[128*24];
    __shared__ __align__(16) __half Wlo_s[128*24];
    __shared__ __align__(16) __half Xhi_s[16*EPS];
    __shared__ __align__(16) __half Xlo_s[16*EPS];

    int tid = threadIdx.x;
    int lane = tid & 31, wid = tid >> 5;
    int wm = wid & 3, wn = wid >> 2;
    int px0 = blockIdx.x * 64;
    int gy  = blockIdx.y;
    int gate = gy >> 1, hh = gy & 1;
    int bi = blockIdx.z;

    const float* bias = gate ? b2 : b1;
    float* outb       = gate ? g_a2 : g_a1;
    int halfoff       = gate ? C : 0;

    float acc[2][4][4];
    #pragma unroll
    for (int m = 0; m < 2; m++)
        #pragma unroll
        for (int n = 0; n < 4; n++)
            #pragma unroll
            for (int r = 0; r < 4; r++) acc[m][n][r] = 0.f;

    int ic_l = tid >> 4;
    int n0   = (tid & 15)*4;

    int a_row = (lane & 7) + ((lane >> 3) & 1)*8;
    int a_col = (lane >> 4)*8;
    int k_l  = (lane & 7) + ((lane >> 3) & 1)*8;
    int nsel = ((lane >> 4) & 1)*8;

    #pragma unroll
    for (int ch = 0; ch < 4; ch++) {
        __syncthreads();
        {
            const float* src = g_fusion + ((size_t)(bi*C2 + halfoff + ch*16 + ic_l))*HW + px0 + n0;
            float4 v = *((const float4*)src);
            float vv[4] = {v.x, v.y, v.z, v.w};
            __align__(8) __half hv[4], lv[4];
            #pragma unroll
            for (int j = 0; j < 4; j++) split2(vv[j], hv[j], lv[j]);
            *((uint2*)(Xhi_s + ic_l*EPS + n0)) = *((uint2*)hv);
            *((uint2*)(Xlo_s + ic_l*EPS + n0)) = *((uint2*)lv);
        }
        {
            const float4* sH = (const float4*)(g_pwhi + ((size_t)(gate*4 + ch)*256 + hh*128)*24);
            const float4* sL = (const float4*)(g_pwlo + ((size_t)(gate*4 + ch)*256 + hh*128)*24);
            ((float4*)Whi_s)[tid] = sH[tid];
            ((float4*)Wlo_s)[tid] = sL[tid];
            if (tid < 128) {
                ((float4*)Whi_s)[256 + tid] = sH[256 + tid];
                ((float4*)Wlo_s)[256 + tid] = sL[256 + tid];
            }
        }
        __syncthreads();

        unsigned Ahi[2][4], Alo[2][4];
        ldsm4(Ahi[0], &Whi_s[(wm*32 +      a_row)*24 + a_col]);
        ldsm4(Ahi[1], &Whi_s[(wm*32 + 16 + a_row)*24 + a_col]);
        ldsm4(Alo[0], &Wlo_s[(wm*32 +      a_row)*24 + a_col]);
        ldsm4(Alo[1], &Wlo_s[(wm*32 + 16 + a_row)*24 + a_col]);
        unsigned Bhi[4][2], Blo[4][2];
        #pragma unroll
        for (int p = 0; p < 2; p++) {
            unsigned t[4];
            ldsm4t(t, &Xhi_s[k_l*EPS + wn*32 + p*16 + nsel]);
            Bhi[2*p][0] = t[0]; Bhi[2*p][1] = t[1];
            Bhi[2*p+1][0] = t[2]; Bhi[2*p+1][1] = t[3];
            ldsm4t(t, &Xlo_s[k_l*EPS + wn*32 + p*16 + nsel]);
            Blo[2*p][0] = t[0]; Blo[2*p][1] = t[1];
            Blo[2*p+1][0] = t[2]; Blo[2*p+1][1] = t[3];
        }
        #pragma unroll
        for (int m = 0; m < 2; m++)
            #pragma unroll
            for (int n = 0; n < 4; n++) {
                mma16816(acc[m][n], Ahi[m], Bhi[n]);
                mma16816(acc[m][n], Ahi[m], Blo[n]);
                mma16816(acc[m][n], Alo[m], Bhi[n]);
            }
    }

    int row_ = lane >> 2;
    int colp = (lane & 3)*2;
    #pragma unroll
    for (int m = 0; m < 2; m++) {
        int ocA = hh*128 + wm*32 + m*16 + row_;
        int ocB = ocA + 8;
        float bA = bias[ocA], bB = bias[ocB];
        #pragma unroll
        for (int n = 0; n < 4; n++) {
            int xo = px0 + wn*32 + n*8 + colp;
            *((float2*)(outb + ((size_t)bi*C4 + ocA)*HW + xo)) =
                make_float2(acc[m][n][0] + bA, acc[m][n][1] + bA);
            *((float2*)(outb + ((size_t)bi*C4 + ocB)*HW + xo)) =
                make_float2(acc[m][n][2] + bB, acc[m][n][3] + bB);
        }
    }
}

// ---------------- fused dw3x3 + BOTH-gate contract + sigmoid + combine ------------
// B operand built INLINE: per (ic, 8px) load 3 rows of g_a (flat px, y=p±W),
// compute 9-tap dw + bias, split fp16, store conflict-free. Then mma as R14.
// Flat 8-px groups never cross a row (W % 8 == 0); only x==0 / x==W-1 masked.
#define CPS 136
__global__ void __launch_bounds__(256, 2) contract_both_kernel(const float* __restrict__ dw1_w,
                                                               const float* __restrict__ dw1_b,
                                                               const float* __restrict__ dw2_w,
                                                               const float* __restrict__ dw2_b,
                                                               const float* __restrict__ po1_b,
                                                               const float* __restrict__ po2_b,
                                                               float* __restrict__ outbase) {
    __shared__ __align__(16) __half Ahi_s[2][64*24];
    __shared__ __align__(16) __half Alo_s[2][64*24];
    __shared__ __align__(16) __half Bhi_s[2][16*CPS];
    __shared__ __align__(16) __half Blo_s[2][16*CPS];

    int tid = threadIdx.x;
    int lane = tid & 31, wid = tid >> 5;
    int wm = wid & 1, wn = wid >> 1;
    int px0 = blockIdx.x * 128;
    int bi = blockIdx.y;

    float acc[2][2][4][4];
    #pragma unroll
    for (int gg = 0; gg < 2; gg++)
        #pragma unroll
        for (int m = 0; m < 2; m++)
            #pragma unroll
            for (int n = 0; n < 4; n++)
                #pragma unroll
                for (int r = 0; r < 4; r++) acc[gg][m][n][r] = 0.f;

    int ic_l = tid >> 4;
    int n0   = (tid & 15)*8;

    // dw geometry for this thread's 8-px group (ch-invariant)
    int flat0 = px0 + n0;
    int ycoord = flat0 / W;
    int xg = flat0 - ycoord*W;                 // multiple of 8
    bool topok = ycoord > 0, botok = ycoord < H-1;
    bool lok = xg > 0, rok = xg + 8 < W;

    int a_row = (lane & 7) + ((lane >> 3) & 1)*8;
    int a_col = (lane >> 4)*8;
    int k_l  = (lane & 7) + ((lane >> 3) & 1)*8;
    int nsel = ((lane >> 4) & 1)*8;

    for (int ch = 0; ch < 16; ch++) {
        __syncthreads();
        // ---- inline dw: per gate, load 3 rows x 10 px of g_a, 9-tap + bias, split
        {
            int icg = ch*16 + ic_l;                       // channel 0..255
            size_t pbase = ((size_t)(bi*C4 + icg))*HW + (size_t)ycoord*W + xg;
            #pragma unroll
            for (int gg = 0; gg < 2; gg++) {
                const float* ab = (gg ? g_a2 : g_a1) + pbase;
                const float* wp = (gg ? dw2_w : dw1_w) + icg*9;
                float w[9];
                #pragma unroll
                for (int k = 0; k < 9; k++) w[k] = wp[k];
                float A[3][10];
                #pragma unroll
                for (int r = 0; r < 3; r++) {
                    bool rowok = (r == 1) || (r == 0 ? topok : botok);
                    if (rowok) {
                        const float* row = ab + (r - 1)*W;
                        float4 m0 = ((const float4*)row)[0];
                        float4 m1 = ((const float4*)row)[1];
                        A[r][0] = lok ? row[-1] : 0.f;
                        A[r][1] = m0.x; A[r][2] = m0.y; A[r][3] = m0.z; A[r][4] = m0.w;
                        A[r][5] = m1.x; A[r][6] = m1.y; A[r][7] = m1.z; A[r][8] = m1.w;
                        A[r][9] = rok ? row[8] : 0.f;
                    } else {
                        #pragma unroll
                        for (int j = 0; j < 10; j++) A[r][j] = 0.f;
                    }
                }
                float bv = (gg ? dw2_b : dw1_b)[icg];
                __align__(16) __half hv[8], lv[8];
                #pragma unroll
                for (int j = 0; j < 8; j++) {
                    float s = bv;
                    #pragma unroll
                    for (int r = 0; r < 3; r++)
                        #pragma unroll
                        for (int c2 = 0; c2 < 3; c2++)
                            s = fmaf(A[r][j + c2], w[r*3 + c2], s);
                    split2(s, hv[j], lv[j]);
                }
                *((uint4*)(Bhi_s[gg] + ic_l*CPS + n0)) = *((uint4*)hv);
                *((uint4*)(Blo_s[gg] + ic_l*CPS + n0)) = *((uint4*)lv);
            }
        }
        if (tid < 192) {
            ((float4*)Ahi_s[0])[tid] = ((const float4*)(g_cwhi + ((size_t)(0*16 + ch)*64)*24))[tid];
            ((float4*)Alo_s[0])[tid] = ((const float4*)(g_cwlo + ((size_t)(0*16 + ch)*64)*24))[tid];
            ((float4*)Ahi_s[1])[tid] = ((const float4*)(g_cwhi + ((size_t)(1*16 + ch)*64)*24))[tid];
            ((float4*)Alo_s[1])[tid] = ((const float4*)(g_cwlo + ((size_t)(1*16 + ch)*64)*24))[tid];
        }
        __syncthreads();

        #pragma unroll
        for (int gg = 0; gg < 2; gg++) {
            unsigned Ahi[2][4], Alo[2][4];
            ldsm4(Ahi[0], &Ahi_s[gg][(wm*32 +      a_row)*24 + a_col]);
            ldsm4(Ahi[1], &Ahi_s[gg][(wm*32 + 16 + a_row)*24 + a_col]);
            ldsm4(Alo[0], &Alo_s[gg][(wm*32 +      a_row)*24 + a_col]);
            ldsm4(Alo[1], &Alo_s[gg][(wm*32 + 16 + a_row)*24 + a_col]);
            unsigned Bhi[4][2], Blo[4][2];
            #pragma unroll
            for (int p = 0; p < 2; p++) {
                unsigned t[4];
                ldsm4t(t, &Bhi_s[gg][k_l*CPS + wn*32 + p*16 + nsel]);
                Bhi[2*p][0] = t[0]; Bhi[2*p][1] = t[1];
                Bhi[2*p+1][0] = t[2]; Bhi[2*p+1][1] = t[3];
                ldsm4t(t, &Blo_s[gg][k_l*CPS + wn*32 + p*16 + nsel]);
                Blo[2*p][0] = t[0]; Blo[2*p][1] = t[1];
                Blo[2*p+1][0] = t[2]; Blo[2*p+1][1] = t[3];
            }
            #pragma unroll
            for (int m = 0; m < 2; m++)
                #pragma unroll
                for (int n = 0; n < 4; n++) {
                    mma16816(acc[gg][m][n], Ahi[m], Bhi[n]);
                    mma16816(acc[gg][m][n], Ahi[m], Blo[n]);
                    mma16816(acc[gg][m][n], Alo[m], Bhi[n]);
                }
        }
    }

    int row_ = lane >> 2;
    int colp = (lane & 3)*2;
    #pragma unroll
    for (int m = 0; m < 2; m++) {
        int ocA = wm*32 + m*16 + row_;
        int ocB = ocA + 8;
        float b1A = po1_b[ocA], b1B = po1_b[ocB];
        float b2A = po2_b[ocA], b2B = po2_b[ocB];
        #pragma unroll
        for (int n = 0; n < 4; n++) {
            int xo = px0 + wn*32 + n*8 + colp;
            float g1A0 = 1.0f / (1.0f + __expf(-(acc[0][m][n][0] + b1A)));
            float g1A1 = 1.0f / (1.0f + __expf(-(acc[0][m][n][1] + b1A)));
            float g1B0 = 1.0f / (1.0f + __expf(-(acc[0][m][n][2] + b1B)));
            float g1B1 = 1.0f / (1.0f + __expf(-(acc[0][m][n][3] + b1B)));
            float g2A0 = 1.0f / (1.0f + __expf(-(acc[1][m][n][0] + b2A)));
            float g2A1 = 1.0f / (1.0f + __expf(-(acc[1][m][n][1] + b2A)));
            float g2B0 = 1.0f / (1.0f + __expf(-(acc[1][m][n][2] + b2B)));
            float g2B1 = 1.0f / (1.0f + __expf(-(acc[1][m][n][3] + b2B)));
            float2 f1A = *((const float2*)(g_fusion + ((size_t)bi*C2 + ocA)*HW + xo));
            float2 f2A = *((const float2*)(g_fusion + ((size_t)bi*C2 + C + ocA)*HW + xo));
            float2 f1B = *((const float2*)(g_fusion + ((size_t)bi*C2 + ocB)*HW + xo));
            float2 f2B = *((const float2*)(g_fusion + ((size_t)bi*C2 + C + ocB)*HW + xo));
            *((float2*)(outbase + (size_t)bi*TCHW + (size_t)ocA*HW + xo)) =
                make_float2(f1A.x*g1A0 + f2A.x*g2A0, f1A.y*g1A1 + f2A.y*g2A1);
            *((float2*)(outbase + (size_t)bi*TCHW + (size_t)ocB*HW + xo)) =
                make_float2(f1B.x*g1B0 + f2B.x*g2B0, f1B.y*g1B1 + f2B.y*g2B1);
        }
    }
}

// ---------------- launcher -------------------------------------------------------
extern "C" void kernel_launch(void* const* d_in, const int* in_sizes, int n_in,
                              void* d_out, int out_size) {
    (void)in_sizes; (void)n_in; (void)out_size;
    const float* feature   = (const float*)d_in[0];
    const float* kc_w1     = (const float*)d_in[1];
    const float* kc_gamma  = (const float*)d_in[2];
    const float* kc_beta   = (const float*)d_in[3];
    const float* kc_mean   = (const float*)d_in[4];
    const float* kc_var    = (const float*)d_in[5];
    const float* kc_w2     = (const float*)d_in[6];
    const float* kc_b2     = (const float*)d_in[7];
    const float* kc_bias   = (const float*)d_in[8];
    const float* conv1_w   = (const float*)d_in[9];
    const float* conv1_b   = (const float*)d_in[10];
    const float* pi1_w     = (const float*)d_in[11];
    const float* pi1_b     = (const float*)d_in[12];
    const float* dw1_w     = (const float*)d_in[13];
    const float* dw1_b     = (const float*)d_in[14];
    const float* po1_w     = (const float*)d_in[15];
    const float* po1_b     = (const float*)d_in[16];
    const float* pi2_w     = (const float*)d_in[17];
    const float* pi2_b     = (const float*)d_in[18];
    const float* dw2_w     = (const float*)d_in[19];
    const float* dw2_b     = (const float*)d_in[20];
    const float* po2_w     = (const float*)d_in[21];
    const float* po2_b     = (const float*)d_in[22];
    float* out = (float*)d_out;

    static bool attr_done = false;
    if (!attr_done) {
        cudaFuncSetAttribute(conv_mma_kernel, cudaFuncAttributeMaxDynamicSharedMemorySize, CONV_SMEM);
        attr_done = true;
    }

    // out[:, T-1] = feature[:, T-1]
    for (int bi = 0; bi < BATCH; bi++) {
        size_t off = ((size_t)bi*T + (T-1)) * CHW;
        cudaMemcpyAsync(out + off, feature + off, (size_t)CHW*sizeof(float),
                        cudaMemcpyDeviceToDevice, 0);
    }

    // one-time: weight splits + ALL per-step dynamic weights
    prep_w_kernel<<<(9*8*128*16 + 255)/256, 256>>>(conv1_w);
    prep_pw_kernel<<<(2*4*256*16 + 255)/256, 256>>>(pi1_w, pi2_w);
    prep_cw_kernel<<<(2*16*64*16 + 255)/256, 256>>>(po1_w, po2_w);
    pool_all_kernel<<<(T-1)*BATCH*C, 256>>>(feature);
    mlp_all_kernel<<<T-1, 128>>>(kc_w1, kc_gamma, kc_beta, kc_mean, kc_var, kc_w2, kc_b2);

    for (int i = T - 2; i >= 0; --i) {
        const float* xbase = feature + (size_t)i*CHW;
        const float* ybase = out + (size_t)(i+1)*CHW;

        dyndw_kernel<<<(BATCH*CHW/4)/256, 256>>>(ybase, kc_bias, i);
        conv_mma_kernel<<<dim3(W/32, H/4, BATCH), 512, CONV_SMEM>>>(xbase, conv1_b);
        expand_mma_kernel<<<dim3(HW/64, 4, BATCH), 256>>>(pi1_b, pi2_b);
        contract_both_kernel<<<dim3(HW/128, BATCH), 256>>>(dw1_w, dw1_b, dw2_w, dw2_b,
                                                           po1_b, po2_b, out + (size_t)i*CHW);
    }
}